// round 13
// baseline (speedup 1.0000x reference)
#include <cuda_runtime.h>
#include <math.h>

#define NUM_EMB 512
#define DIM 64
#define NPTS 131072          // 32*64*64 spatial points
#define TPB 256
#define NBLK (NPTS / TPB)    // 512 blocks
#define HW 4096              // 64*64
#define CHUNK 256            // codes resident in smem at a time (2 chunks)

// Output layout (fp32): [loss(1) | quantized NCHW(8388608) | perplexity(1) | encodings(131072*512)]
#define Q_ELEMS 8388608
#define FULL_OUT 75497474

// Scratch (no allocations allowed). g_hist is zero at load; vq_zero re-zeros it
// after each consume so every graph replay sees a clean histogram.
__device__ float g_partial[NBLK];
__device__ int   g_hist[NUM_EMB];

// ---------------- f32x2 helpers (FFMA2 path, sm_100+) ----------------
__device__ __forceinline__ unsigned long long pack2(float lo, float hi) {
    unsigned long long r;
    asm("mov.b64 %0, {%1, %2};" : "=l"(r) : "f"(lo), "f"(hi));
    return r;
}
__device__ __forceinline__ void unpack2(unsigned long long v, float& lo, float& hi) {
    asm("mov.b64 {%0, %1}, %2;" : "=f"(lo), "=f"(hi) : "l"(v));
}
__device__ __forceinline__ void fma2(unsigned long long& acc, unsigned long long a, unsigned long long b) {
    asm("fma.rn.f32x2 %0, %1, %2, %0;" : "+l"(acc) : "l"(a), "l"(b));
}
__device__ __forceinline__ unsigned long long add2(unsigned long long a, unsigned long long b) {
    unsigned long long r;
    asm("add.rn.f32x2 %0, %1, %2;" : "=l"(r) : "l"(a), "l"(b));
    return r;
}

// ---------------- main kernel ----------------
// Chunked codebook: only 256 codes (64KB) resident -> smem/CTA ~68KB, regs<=128
// -> 2 CTAs/SM (16 warps) for latency hiding.
// SMEM layout:
//   s_e   : 256 codes * 32 dim-pairs * 8B = 65536 B   (current chunk)
//   s_hn  : 512 * 4B   (-0.5*||e_k||^2, all codes)
//   s_kmin: 256 * 4B
//   s_red : 256 * 4B
#define SMEM_BYTES (65536 + 2048 + 1024 + 1024)

extern __shared__ unsigned char s_raw[];

__global__ __launch_bounds__(TPB, 2)
void vq_main(const float* __restrict__ x,
             const float* __restrict__ emb,
             float* __restrict__ out_q,
             float* __restrict__ out_enc,
             int write_aux) {
    unsigned long long* s_e = (unsigned long long*)s_raw;    // CHUNK*32 pairs
    float* s_hn  = (float*)(s_e + CHUNK * 32);               // 512
    int*   s_kmin = (int*)(s_hn + NUM_EMB);                  // 256
    float* s_red  = (float*)(s_kmin + TPB);                  // 256

    const int tid = threadIdx.x;

    // ---- all-code half-norms from gmem (emb is L2-hot, 2 rows/thread) ----
    for (int k = tid; k < NUM_EMB; k += TPB) {
        const float4* row = (const float4*)(emb + k * DIM);
        float nrm = 0.f;
        #pragma unroll
        for (int i = 0; i < 16; i++) {
            float4 v = row[i];
            nrm += v.x * v.x + v.y * v.y + v.z * v.z + v.w * v.w;
        }
        s_hn[k] = -0.5f * nrm;
    }

    // ---- load this thread's point z as 32 dim-pairs (64 regs) ----
    const int n = blockIdx.x * TPB + tid;
    const int base = ((n >> 12) << 18) + (n & (HW - 1));   // b*262144 + h*64 + w
    unsigned long long zp[32];
    #pragma unroll
    for (int d2 = 0; d2 < 32; d2++) {
        zp[d2] = pack2(x[base + ((2 * d2) << 12)], x[base + ((2 * d2 + 1) << 12)]);
    }

    // ---- argmax over s_k = z.e_k - 0.5||e_k||^2, chunked over the codebook ----
    float best = -3.4e38f;
    int bestk = 0;
    for (int c = 0; c < NUM_EMB / CHUNK; c++) {
        __syncthreads();   // previous chunk's readers done before refill (also orders s_hn on c=0)
        for (int idx = tid; idx < CHUNK * 32; idx += TPB) {
            const float* ep = emb + (c * CHUNK + (idx >> 5)) * DIM + ((idx & 31) * 2);
            s_e[idx] = pack2(ep[0], ep[1]);
        }
        __syncthreads();

        const int kb = c * CHUNK;
        for (int k2 = 0; k2 < CHUNK; k2 += 2) {
            const ulonglong2* eA = (const ulonglong2*)(s_e + (k2 << 5));
            const ulonglong2* eB = (const ulonglong2*)(s_e + ((k2 + 1) << 5));
            unsigned long long a0 = 0ull, a1 = 0ull, b0 = 0ull, b1 = 0ull;
            #pragma unroll
            for (int i = 0; i < 16; i++) {
                ulonglong2 vA = eA[i];
                ulonglong2 vB = eB[i];
                fma2(a0, zp[2 * i],     vA.x);
                fma2(a1, zp[2 * i + 1], vA.y);
                fma2(b0, zp[2 * i],     vB.x);
                fma2(b1, zp[2 * i + 1], vB.y);
            }
            float l, h;
            unpack2(add2(a0, a1), l, h);
            float sc0 = l + h + s_hn[kb + k2];
            unpack2(add2(b0, b1), l, h);
            float sc1 = l + h + s_hn[kb + k2 + 1];
            if (sc0 > best) { best = sc0; bestk = kb + k2; }
            if (sc1 > best) { best = sc1; bestk = kb + k2 + 1; }
        }
    }

    s_kmin[tid] = bestk;
    atomicAdd(&g_hist[bestk], 1);   // int atomics: order-invariant -> deterministic

    // ---- gather winning code from gmem (L2-hot), scatter + loss partial ----
    float lsum = 0.f;
    {
        const float4* er = (const float4*)(emb + bestk * DIM);
        #pragma unroll
        for (int i = 0; i < 16; i++) {
            float4 e = er[i];
            float z0, z1, z2, z3;
            unpack2(zp[2 * i],     z0, z1);
            unpack2(zp[2 * i + 1], z2, z3);
            float d0 = e.x - z0, d1 = e.y - z1, d2 = e.z - z2, d3 = e.w - z3;
            lsum += d0 * d0 + d1 * d1 + d2 * d2 + d3 * d3;
            out_q[base + ((4 * i)     << 12)] = e.x;
            out_q[base + ((4 * i + 1) << 12)] = e.y;
            out_q[base + ((4 * i + 2) << 12)] = e.z;
            out_q[base + ((4 * i + 3) << 12)] = e.w;
        }
    }

    // ---- deterministic fixed-order block reduction of loss partials ----
    s_red[tid] = lsum;
    __syncthreads();
    #pragma unroll
    for (int s = 128; s > 0; s >>= 1) {
        if (tid < s) s_red[tid] += s_red[tid + s];
        __syncthreads();
    }
    if (tid == 0) g_partial[blockIdx.x] = s_red[0];

    // ---- warp-cooperative coalesced one-hot encodings write ----
    // NOTE: out_enc is only 8-byte aligned (base offset 2+Q_ELEMS floats ≡ 8 mod 16),
    // so stores must be float2 (STG.64), never float4.
    if (write_aux) {
        float* enc = out_enc + (size_t)blockIdx.x * TPB * NUM_EMB;
        const int warp = tid >> 5, lane = tid & 31;
        for (int r = warp; r < TPB; r += 8) {
            int kb = s_kmin[r];
            float2* rowp = (float2*)(enc + (size_t)r * NUM_EMB);
            #pragma unroll
            for (int q2 = 0; q2 < 8; q2++) {
                int col = q2 * 64 + lane * 2;            // 256B contiguous per q2 across warp
                float2 v = make_float2(0.f, 0.f);
                unsigned rel = (unsigned)(kb - col);
                if (rel < 2u) ((float*)&v)[rel] = 1.0f;
                rowp[col >> 1] = v;
            }
        }
    }
}

// ---------------- finalize: loss scalar + perplexity ----------------
__global__ void vq_final(float* __restrict__ loss_out, float* __restrict__ perp_out) {
    __shared__ double sh[512];
    const int t = threadIdx.x;

    sh[t] = (t < NBLK) ? (double)g_partial[t] : 0.0;
    __syncthreads();
    for (int s = 256; s > 0; s >>= 1) { if (t < s) sh[t] += sh[t + s]; __syncthreads(); }
    if (t == 0) *loss_out = (float)(0.25 * sh[0] / (double)Q_ELEMS);
    __syncthreads();

    {
        double p = (double)g_hist[t] / (double)NPTS;
        sh[t] = p * log(p + 1e-10);
    }
    __syncthreads();
    for (int s = 256; s > 0; s >>= 1) { if (t < s) sh[t] += sh[t + s]; __syncthreads(); }
    if (t == 0) *perp_out = (float)exp(-sh[0]);
}

// ---------------- zero the histogram for the next replay ----------------
__global__ void vq_zero() {
    g_hist[threadIdx.x] = 0;
}

// ---------------- launch ----------------
// Order (main, final, zero): keeps vq_main in ncu's captured slot, and g_hist is
// consumed before being re-zeroed for the next deterministic replay.
extern "C" void kernel_launch(void* const* d_in, const int* in_sizes, int n_in,
                              void* d_out, int out_size) {
    const float* x   = (const float*)d_in[0];
    const float* emb = (const float*)d_in[1];
    float* out = (float*)d_out;

    const bool full = (out_size >= FULL_OUT);
    float* out_loss = full ? out : nullptr;
    float* out_q    = full ? out + 1 : out;             // fallback: quantized-only output
    float* out_perp = full ? out + 1 + Q_ELEMS : nullptr;
    float* out_enc  = full ? out + 2 + Q_ELEMS : nullptr;

    cudaFuncSetAttribute(vq_main, cudaFuncAttributeMaxDynamicSharedMemorySize, SMEM_BYTES);

    vq_main<<<NBLK, TPB, SMEM_BYTES>>>(x, emb, out_q, out_enc, full ? 1 : 0);
    if (full) vq_final<<<1, 512>>>(out_loss, out_perp);
    vq_zero<<<1, NUM_EMB>>>();
}

// round 17
// speedup vs baseline: 1.0812x; 1.0812x over previous
#include <cuda_runtime.h>
#include <math.h>

#define NUM_EMB 512
#define DIM 64
#define NPTS 131072          // 32*64*64 spatial points
#define TPB 256
#define PPT 2                // points per thread
#define PTS_PER_CTA (TPB * PPT)          // 512
#define NBLK (NPTS / PTS_PER_CTA)        // 256 blocks
#define HW 4096              // 64*64

// Output layout (fp32): [loss(1) | quantized NCHW(8388608) | perplexity(1) | encodings(131072*512)]
#define Q_ELEMS 8388608
#define FULL_OUT 75497474

// Scratch (no allocations allowed). g_hist is zero at load; it is re-zeroed after
// each consume (vq_final in full mode, vq_zero otherwise) for deterministic replay.
__device__ float g_partial[NBLK];
__device__ int   g_hist[NUM_EMB];

// ---------------- f32x2 helpers (FFMA2 path, sm_100+) ----------------
__device__ __forceinline__ unsigned long long pack2(float lo, float hi) {
    unsigned long long r;
    asm("mov.b64 %0, {%1, %2};" : "=l"(r) : "f"(lo), "f"(hi));
    return r;
}
__device__ __forceinline__ void unpack2(unsigned long long v, float& lo, float& hi) {
    asm("mov.b64 {%0, %1}, %2;" : "=f"(lo), "=f"(hi) : "l"(v));
}
__device__ __forceinline__ void fma2(unsigned long long& acc, unsigned long long a, unsigned long long b) {
    asm("fma.rn.f32x2 %0, %1, %2, %0;" : "+l"(acc) : "l"(a), "l"(b));
}
__device__ __forceinline__ unsigned long long add2(unsigned long long a, unsigned long long b) {
    unsigned long long r;
    asm("add.rn.f32x2 %0, %1, %2;" : "=l"(r) : "l"(a), "l"(b));
    return r;
}

// ---------------- main kernel ----------------
// SMEM layout (dim-pair packing: s_e[k][d2] = (e_k[2*d2], e_k[2*d2+1])):
//   s_e   : 512 codes * 32 dim-pairs * 8B = 131072 B
//   s_hn  : 512 * 4B   (-0.5*||e_k||^2)   [also absorbs the one harmless
//                       one-past-the-end prefetch of the pipelined loop]
//   s_kmin: 512 * 4B
//   s_red : 256 * 4B
#define SMEM_BYTES (131072 + 2048 + 2048 + 1024)

extern __shared__ unsigned char s_raw[];

__global__ __launch_bounds__(TPB, 1)
void vq_main(const float* __restrict__ x,
             const float* __restrict__ emb,
             float* __restrict__ out_q,
             float* __restrict__ out_enc,
             int write_aux) {
    unsigned long long* s_e = (unsigned long long*)s_raw;    // 512*32 pairs
    float* s_hn  = (float*)(s_e + NUM_EMB * 32);             // 512
    int*   s_kmin = (int*)(s_hn + NUM_EMB);                  // 512
    float* s_red  = (float*)(s_kmin + PTS_PER_CTA);          // 256

    const int tid = threadIdx.x;

    // ---- cooperative fill of dim-pair code table ----
    for (int idx = tid; idx < NUM_EMB * 32; idx += TPB) {
        const float* ep = emb + ((idx >> 5) * DIM) + ((idx & 31) * 2);
        s_e[idx] = pack2(ep[0], ep[1]);
    }
    __syncthreads();

    // ---- per-code half-norms (2 codes per thread) ----
    for (int k = tid; k < NUM_EMB; k += TPB) {
        const unsigned long long* row = s_e + (k << 5);
        float nrm = 0.f;
        #pragma unroll 8
        for (int i = 0; i < 32; i++) {
            float a, b; unpack2(row[i], a, b);
            nrm += a * a + b * b;
        }
        s_hn[k] = -0.5f * nrm;
    }

    // ---- load TWO points per thread as dim-pairs (2 * 64 regs) ----
    const int n0 = blockIdx.x * PTS_PER_CTA + tid;
    const int n1 = n0 + TPB;
    const int base0 = ((n0 >> 12) << 18) + (n0 & (HW - 1));
    const int base1 = ((n1 >> 12) << 18) + (n1 & (HW - 1));
    unsigned long long zp0[32], zp1[32];
    #pragma unroll
    for (int d2 = 0; d2 < 32; d2++) {
        zp0[d2] = pack2(x[base0 + ((2 * d2) << 12)], x[base0 + ((2 * d2 + 1) << 12)]);
        zp1[d2] = pack2(x[base1 + ((2 * d2) << 12)], x[base1 + ((2 * d2 + 1) << 12)]);
    }
    __syncthreads();

    // ---- argmax over s_k = z.e_k - 0.5||e_k||^2 for both points ----
    // Software-pipelined (distance-1) LDS: each iteration prefetches the NEXT
    // quad pair (including across code-pair boundaries: stride +17 ull2 at the
    // wrap) before consuming the current one, hiding the 29-cyc LDS latency
    // behind the 8 FFMA2 of the current step. 8 independent f32x2 chains.
    float best0 = -3.4e38f, best1 = -3.4e38f;
    int bk0 = 0, bk1 = 0;
    {
        const ulonglong2* pa = (const ulonglong2*)s_e;        // code k   quads (16 per code)
        const ulonglong2* pb = pa + 16;                        // code k+1 quads
        ulonglong2 vA = pa[0];
        ulonglong2 vB = pb[0];
        for (int k = 0; k < NUM_EMB; k += 2) {
            unsigned long long c00 = 0ull, c01 = 0ull, c02 = 0ull, c03 = 0ull;   // point 0
            unsigned long long c10 = 0ull, c11 = 0ull, c12 = 0ull, c13 = 0ull;   // point 1
            #pragma unroll
            for (int i = 0; i < 16; i++) {
                // prefetch next quads (i<15: next i; i==15: first quads of next k-pair,
                // +17 ull2 past current. Final prefetch lands one slot past s_e into
                // s_hn — in-allocation, value unused.)
                const int stepn = (i < 15) ? 1 : 17;
                ulonglong2 nA = pa[stepn];
                ulonglong2 nB = pb[stepn];
                fma2(c00, zp0[2 * i],     vA.x);
                fma2(c01, zp0[2 * i + 1], vA.y);
                fma2(c02, zp0[2 * i],     vB.x);
                fma2(c03, zp0[2 * i + 1], vB.y);
                fma2(c10, zp1[2 * i],     vA.x);
                fma2(c11, zp1[2 * i + 1], vA.y);
                fma2(c12, zp1[2 * i],     vB.x);
                fma2(c13, zp1[2 * i + 1], vB.y);
                vA = nA; vB = nB;
                pa++; pb++;
            }
            pa += 16; pb += 16;   // skip over the partner row into the next code pair

            const float hA = s_hn[k];
            const float hB = s_hn[k + 1];
            float l, h, sc;
            unpack2(add2(c00, c01), l, h); sc = l + h + hA;
            if (sc > best0) { best0 = sc; bk0 = k; }
            unpack2(add2(c02, c03), l, h); sc = l + h + hB;
            if (sc > best0) { best0 = sc; bk0 = k + 1; }
            unpack2(add2(c10, c11), l, h); sc = l + h + hA;
            if (sc > best1) { best1 = sc; bk1 = k; }
            unpack2(add2(c12, c13), l, h); sc = l + h + hB;
            if (sc > best1) { best1 = sc; bk1 = k + 1; }
        }
    }

    s_kmin[tid]       = bk0;
    s_kmin[tid + TPB] = bk1;
    atomicAdd(&g_hist[bk0], 1);     // int atomics: order-invariant -> deterministic
    atomicAdd(&g_hist[bk1], 1);

    // ---- quantized scatter (coalesced per channel) + commitment-loss partials ----
    float lsum = 0.f;
    {
        const unsigned long long* er0 = s_e + (bk0 << 5);
        const unsigned long long* er1 = s_e + (bk1 << 5);
        #pragma unroll 8
        for (int d2 = 0; d2 < 32; d2++) {
            float e0, e1, z0, z1, d0, d1;
            unpack2(er0[d2], e0, e1); unpack2(zp0[d2], z0, z1);
            d0 = e0 - z0; d1 = e1 - z1; lsum += d0 * d0 + d1 * d1;
            out_q[base0 + ((2 * d2)     << 12)] = e0;
            out_q[base0 + ((2 * d2 + 1) << 12)] = e1;
            unpack2(er1[d2], e0, e1); unpack2(zp1[d2], z0, z1);
            d0 = e0 - z0; d1 = e1 - z1; lsum += d0 * d0 + d1 * d1;
            out_q[base1 + ((2 * d2)     << 12)] = e0;
            out_q[base1 + ((2 * d2 + 1) << 12)] = e1;
        }
    }

    // ---- deterministic fixed-order block reduction of loss partials ----
    s_red[tid] = lsum;
    __syncthreads();
    #pragma unroll
    for (int s = 128; s > 0; s >>= 1) {
        if (tid < s) s_red[tid] += s_red[tid + s];
        __syncthreads();
    }
    if (tid == 0) g_partial[blockIdx.x] = s_red[0];

    // ---- warp-cooperative coalesced one-hot encodings write ----
    // NOTE: out_enc is only 8-byte aligned (base offset 2+Q_ELEMS floats ≡ 8 mod 16),
    // so stores must be float2 (STG.64), never float4.
    if (write_aux) {
        float* enc = out_enc + (size_t)blockIdx.x * PTS_PER_CTA * NUM_EMB;
        const int warp = tid >> 5, lane = tid & 31;
        for (int r = warp; r < PTS_PER_CTA; r += 8) {
            int kb = s_kmin[r];
            float2* rowp = (float2*)(enc + (size_t)r * NUM_EMB);
            #pragma unroll
            for (int q2 = 0; q2 < 8; q2++) {
                int col = q2 * 64 + lane * 2;            // 256B contiguous per q2 across warp
                float2 v = make_float2(0.f, 0.f);
                unsigned rel = (unsigned)(kb - col);
                if (rel < 2u) ((float*)&v)[rel] = 1.0f;
                rowp[col >> 1] = v;
            }
        }
    }
}

// ---------------- finalize: loss scalar + perplexity (+ hist re-zero) ----------------
__global__ void vq_final(float* __restrict__ loss_out, float* __restrict__ perp_out) {
    __shared__ double sh[512];
    const int t = threadIdx.x;

    sh[t] = (t < NBLK) ? (double)g_partial[t] : 0.0;
    __syncthreads();
    for (int s = 256; s > 0; s >>= 1) { if (t < s) sh[t] += sh[t + s]; __syncthreads(); }
    if (t == 0) *loss_out = (float)(0.25 * sh[0] / (double)Q_ELEMS);
    __syncthreads();

    {
        double p = (double)g_hist[t] / (double)NPTS;
        sh[t] = p * log(p + 1e-10);
        g_hist[t] = 0;   // consume + reset for the next deterministic replay
    }
    __syncthreads();
    for (int s = 256; s > 0; s >>= 1) { if (t < s) sh[t] += sh[t + s]; __syncthreads(); }
    if (t == 0) *perp_out = (float)exp(-sh[0]);
}

// ---------------- zero the histogram (non-full mode only) ----------------
__global__ void vq_zero() {
    g_hist[threadIdx.x] = 0;
}

// ---------------- launch ----------------
// Order (main, final): keeps vq_main in ncu's captured slot; vq_final both
// consumes and re-zeros g_hist for deterministic graph replay.
extern "C" void kernel_launch(void* const* d_in, const int* in_sizes, int n_in,
                              void* d_out, int out_size) {
    const float* x   = (const float*)d_in[0];
    const float* emb = (const float*)d_in[1];
    float* out = (float*)d_out;

    const bool full = (out_size >= FULL_OUT);
    float* out_loss = full ? out : nullptr;
    float* out_q    = full ? out + 1 : out;             // fallback: quantized-only output
    float* out_perp = full ? out + 1 + Q_ELEMS : nullptr;
    float* out_enc  = full ? out + 2 + Q_ELEMS : nullptr;

    cudaFuncSetAttribute(vq_main, cudaFuncAttributeMaxDynamicSharedMemorySize, SMEM_BYTES);

    vq_main<<<NBLK, TPB, SMEM_BYTES>>>(x, emb, out_q, out_enc, full ? 1 : 0);
    if (full) vq_final<<<1, 512>>>(out_loss, out_perp);
    else      vq_zero<<<1, NUM_EMB>>>();
}